// round 1
// baseline (speedup 1.0000x reference)
#include <cuda_runtime.h>
#include <math.h>

#define B_    2
#define S_    512
#define H_    2048
#define V_    32000
#define BETA_ 0.1f
#define NCHUNK 250          /* V / 128 */
#define MBLK   8            /* (B*S) / 128 */
#define ROWS_PER_COMBO (B_ * S_)   /* 1024 */

__device__ float g_partial[4 * ROWS_PER_COMBO * NCHUNK];  /* ~4 MB scratch */
__device__ float g_tgt_logit[4 * ROWS_PER_COMBO];
__device__ float g_seq_logps[8];

/* ------------------------------------------------------------------ */
/* Kernel 1: fused SGEMM (128x128 tile, K=8 stages, double-buffered)  */
/* + per-row partial sum of exp(logit + bias) + target-logit capture. */
/* ------------------------------------------------------------------ */
__global__ void __launch_bounds__(256, 2)
fused_gemm_lse(const float* __restrict__ xc,  const float* __restrict__ xr,
               const float* __restrict__ rxc, const float* __restrict__ rxr,
               const float* __restrict__ Wp,  const float* __restrict__ bp,
               const float* __restrict__ Wr,  const float* __restrict__ br,
               const int*   __restrict__ tc,  const int*   __restrict__ tr)
{
    const int combo = blockIdx.z;   /* 0=pol-chosen 1=pol-rej 2=ref-chosen 3=ref-rej */
    const float* x    = (combo == 0) ? xc : (combo == 1) ? xr : (combo == 2) ? rxc : rxr;
    const float* w    = (combo < 2) ? Wp : Wr;
    const float* bias = (combo < 2) ? bp : br;
    const int*   tgt  = (combo & 1) ? tr : tc;

    const int m0 = blockIdx.x * 128;   /* m-block fastest -> concurrent blocks share W tiles in L2 */
    const int n0 = blockIdx.y * 128;

    __shared__ float As[2][8][132];    /* pad 132 kills store-phase bank conflicts */
    __shared__ float Bs[2][8][132];
    __shared__ float red[16][128];

    const int tid  = threadIdx.x;
    const int lrow = tid >> 1;         /* 0..127 */
    const int lcol = (tid & 1) << 2;   /* 0 or 4 */

    const float* aptr = x + (size_t)(m0 + lrow) * H_ + lcol;
    const float* bptr = w + (size_t)(n0 + lrow) * H_ + lcol;

    const int ty = tid >> 4;           /* 0..15 : row group  (8 rows)  */
    const int tx = tid & 15;           /* 0..15 : col group  (8 cols)  */

    float acc[8][8];
    #pragma unroll
    for (int i = 0; i < 8; ++i)
        #pragma unroll
        for (int j = 0; j < 8; ++j) acc[i][j] = 0.f;

    /* preload stage 0 */
    float4 ra = *(const float4*)aptr;
    float4 rb = *(const float4*)bptr;
    aptr += 8; bptr += 8;
    As[0][lcol + 0][lrow] = ra.x; As[0][lcol + 1][lrow] = ra.y;
    As[0][lcol + 2][lrow] = ra.z; As[0][lcol + 3][lrow] = ra.w;
    Bs[0][lcol + 0][lrow] = rb.x; Bs[0][lcol + 1][lrow] = rb.y;
    Bs[0][lcol + 2][lrow] = rb.z; Bs[0][lcol + 3][lrow] = rb.w;
    __syncthreads();

    int buf = 0;
    for (int kt = 1; kt < H_ / 8; ++kt) {
        /* issue next-stage global loads first (latency hides under compute) */
        float4 na = *(const float4*)aptr;
        float4 nb = *(const float4*)bptr;
        aptr += 8; bptr += 8;

        #pragma unroll
        for (int k = 0; k < 8; ++k) {
            float4 a0 = *(const float4*)&As[buf][k][ty * 8];
            float4 a1 = *(const float4*)&As[buf][k][ty * 8 + 4];
            float4 b0 = *(const float4*)&Bs[buf][k][tx * 8];
            float4 b1 = *(const float4*)&Bs[buf][k][tx * 8 + 4];
            float av[8] = {a0.x, a0.y, a0.z, a0.w, a1.x, a1.y, a1.z, a1.w};
            float bv[8] = {b0.x, b0.y, b0.z, b0.w, b1.x, b1.y, b1.z, b1.w};
            #pragma unroll
            for (int i = 0; i < 8; ++i)
                #pragma unroll
                for (int j = 0; j < 8; ++j)
                    acc[i][j] = fmaf(av[i], bv[j], acc[i][j]);
        }

        const int nbuf = buf ^ 1;
        As[nbuf][lcol + 0][lrow] = na.x; As[nbuf][lcol + 1][lrow] = na.y;
        As[nbuf][lcol + 2][lrow] = na.z; As[nbuf][lcol + 3][lrow] = na.w;
        Bs[nbuf][lcol + 0][lrow] = nb.x; Bs[nbuf][lcol + 1][lrow] = nb.y;
        Bs[nbuf][lcol + 2][lrow] = nb.z; Bs[nbuf][lcol + 3][lrow] = nb.w;
        __syncthreads();
        buf = nbuf;
    }
    /* last stage compute */
    #pragma unroll
    for (int k = 0; k < 8; ++k) {
        float4 a0 = *(const float4*)&As[buf][k][ty * 8];
        float4 a1 = *(const float4*)&As[buf][k][ty * 8 + 4];
        float4 b0 = *(const float4*)&Bs[buf][k][tx * 8];
        float4 b1 = *(const float4*)&Bs[buf][k][tx * 8 + 4];
        float av[8] = {a0.x, a0.y, a0.z, a0.w, a1.x, a1.y, a1.z, a1.w};
        float bv[8] = {b0.x, b0.y, b0.z, b0.w, b1.x, b1.y, b1.z, b1.w};
        #pragma unroll
        for (int i = 0; i < 8; ++i)
            #pragma unroll
            for (int j = 0; j < 8; ++j)
                acc[i][j] = fmaf(av[i], bv[j], acc[i][j]);
    }

    /* -------- epilogue: exp + per-row partial sums -------- */
    float bj[8];
    #pragma unroll
    for (int j = 0; j < 8; ++j) bj[j] = __ldg(&bias[n0 + tx * 8 + j]);

    float rowsum[8];
    #pragma unroll
    for (int i = 0; i < 8; ++i) {
        float s = 0.f;
        #pragma unroll
        for (int j = 0; j < 8; ++j) s += expf(acc[i][j] + bj[j]);
        rowsum[i] = s;
    }
    #pragma unroll
    for (int i = 0; i < 8; ++i) red[tx][ty * 8 + i] = rowsum[i];
    __syncthreads();

    if (tid < 128) {
        float s = 0.f;
        #pragma unroll
        for (int j = 0; j < 16; ++j) s += red[j][tid];
        g_partial[(size_t)(combo * ROWS_PER_COMBO + m0 + tid) * NCHUNK + blockIdx.y] = s;
    }

    /* -------- target logit capture (single deterministic writer) -------- */
    #pragma unroll
    for (int i = 0; i < 8; ++i) {
        const int row = m0 + ty * 8 + i;           /* row within combo, 0..1023 */
        const int t = __ldg(&tgt[row]);
        if (t >= n0 && t < n0 + 128) {
            const int loc = t - n0;
            if ((loc >> 3) == tx)
                g_tgt_logit[combo * ROWS_PER_COMBO + row] = acc[i][loc & 7] + __ldg(&bias[t]);
        }
    }
}

/* ------------------------------------------------------------------ */
/* Kernel 2: per-(combo,batch) sequence log-prob. Deterministic.       */
/* ------------------------------------------------------------------ */
__global__ void reduce_rows(const int* __restrict__ tc, const int* __restrict__ tr)
{
    const int cb    = blockIdx.x;      /* 0..7 : combo*2 + b */
    const int combo = cb >> 1;
    const int bb    = cb & 1;
    const int* tgt  = (combo & 1) ? tr : tc;

    __shared__ float sdata[256];
    float acc = 0.f;
    for (int s = threadIdx.x; s < S_; s += 256) {
        const int row = bb * S_ + s;
        const int gr  = combo * ROWS_PER_COMBO + row;
        const float* p = &g_partial[(size_t)gr * NCHUNK];
        float sum = 0.f;
        for (int j = 0; j < NCHUNK; ++j) sum += p[j];
        const int t = tgt[row];
        if (t >= 0) acc += g_tgt_logit[gr] - logf(sum);
    }
    sdata[threadIdx.x] = acc;
    __syncthreads();
    for (int off = 128; off > 0; off >>= 1) {
        if (threadIdx.x < off) sdata[threadIdx.x] += sdata[threadIdx.x + off];
        __syncthreads();
    }
    if (threadIdx.x == 0) g_seq_logps[cb] = sdata[0];
}

/* ------------------------------------------------------------------ */
/* Kernel 3: DPO scalars.                                              */
/* ------------------------------------------------------------------ */
__device__ __forceinline__ float log_sigmoid(float z)
{
    return (z >= 0.f) ? -log1pf(expf(-z)) : (z - log1pf(expf(z)));
}

__global__ void finalize(float* __restrict__ out, int out_size)
{
    if (threadIdx.x != 0 || blockIdx.x != 0) return;
    float loss = 0.f, crs = 0.f, rrs = 0.f, margin = 0.f, accc = 0.f;
    for (int b = 0; b < B_; ++b) {
        const float cl  = g_seq_logps[0 + b];   /* policy chosen   */
        const float rl  = g_seq_logps[2 + b];   /* policy rejected */
        const float rcl = g_seq_logps[4 + b];   /* ref chosen      */
        const float rrl = g_seq_logps[6 + b];   /* ref rejected    */
        const float cr = BETA_ * (cl - rcl);
        const float rr = BETA_ * (rl - rrl);
        const float z  = BETA_ * ((cl - rl) - (rcl - rrl));
        loss   += -log_sigmoid(z);
        crs    += cr;
        rrs    += rr;
        margin += cr - rr;
        accc   += (cr > rr) ? 1.f : 0.f;
    }
    const float invB = 1.f / (float)B_;
    float vals[6] = {loss * invB, crs * invB, rrs * invB, margin * invB, accc * invB, 0.f};
    for (int i = 0; i < out_size; ++i) out[i] = (i < 6) ? vals[i] : 0.f;
}

/* ------------------------------------------------------------------ */
extern "C" void kernel_launch(void* const* d_in, const int* in_sizes, int n_in,
                              void* d_out, int out_size)
{
    const float* xc  = (const float*)d_in[0];
    const float* xr  = (const float*)d_in[1];
    const float* rxc = (const float*)d_in[2];
    const float* rxr = (const float*)d_in[3];
    const float* Wp  = (const float*)d_in[4];
    const float* bp  = (const float*)d_in[5];
    const float* Wr  = (const float*)d_in[6];
    const float* br  = (const float*)d_in[7];
    const int*   tc  = (const int*)d_in[8];
    const int*   tr  = (const int*)d_in[9];

    dim3 g1(MBLK, NCHUNK, 4);
    fused_gemm_lse<<<g1, 256>>>(xc, xr, rxc, rxr, Wp, bp, Wr, br, tc, tr);
    reduce_rows<<<8, 256>>>(tc, tr);
    finalize<<<1, 1>>>((float*)d_out, out_size);
}

// round 4
// speedup vs baseline: 4.3813x; 4.3813x over previous
#include <cuda_runtime.h>
#include <cuda_bf16.h>
#include <math.h>
#include <stdint.h>
#include <stddef.h>

#define B_    2
#define S_    512
#define H_    2048
#define V_    32000
#define BETA_ 0.1f

#define MT 128
#define NT 128
#define KCH 64                    /* K elems per stage chunk */
#define KTILES (H_/KCH)           /* 32 */
#define NCHUNK (V_/NT)            /* 250 */
#define ROWS  1024                /* B*S per combo */

/* ---------------- device scratch (static, allocation-free) ---------------- */
__device__ __align__(256) __nv_bfloat16 g_Ah[4u * ROWS * H_];
__device__ __align__(256) __nv_bfloat16 g_Al[4u * ROWS * H_];
__device__ __align__(256) __nv_bfloat16 g_Wh[2u * (size_t)V_ * H_];
__device__ __align__(256) __nv_bfloat16 g_Wl[2u * (size_t)V_ * H_];
__device__ float  g_partial[4u * ROWS * NCHUNK];
__device__ float  g_tgt[4u * ROWS];
__device__ double g_seq[8];

/* ---------------- helpers ---------------- */
__device__ __forceinline__ uint32_t smem_u32(const void* p) {
    uint32_t a;
    asm("{ .reg .u64 t; cvta.to.shared.u64 t, %1; cvt.u32.u64 %0, t; }" : "=r"(a) : "l"(p));
    return a;
}
__device__ __forceinline__ void cpa16(uint32_t dst, const void* src) {
    asm volatile("cp.async.cg.shared.global [%0], [%1], 16;" :: "r"(dst), "l"(src));
}
__device__ __forceinline__ void ldsm4(uint32_t& r0, uint32_t& r1, uint32_t& r2, uint32_t& r3,
                                      uint32_t a) {
    asm volatile("ldmatrix.sync.aligned.m8n8.x4.shared.b16 {%0,%1,%2,%3}, [%4];"
                 : "=r"(r0), "=r"(r1), "=r"(r2), "=r"(r3) : "r"(a));
}
__device__ __forceinline__ void mma16816(float* c, const uint32_t* a, const uint32_t* b) {
    asm volatile(
        "mma.sync.aligned.m16n8k16.row.col.f32.bf16.bf16.f32 "
        "{%0,%1,%2,%3}, {%4,%5,%6,%7}, {%8,%9}, {%0,%1,%2,%3};"
        : "+f"(c[0]), "+f"(c[1]), "+f"(c[2]), "+f"(c[3])
        : "r"(a[0]), "r"(a[1]), "r"(a[2]), "r"(a[3]), "r"(b[0]), "r"(b[1]));
}

/* ---------------- prep: fp32 -> bf16 hi/lo split ---------------- */
__global__ void split_bf16(const float4* __restrict__ src, int which, size_t elem_off, int n4)
{
    int i = blockIdx.x * blockDim.x + threadIdx.x;
    if (i >= n4) return;
    float4 v = src[i];
    __nv_bfloat16 h0 = __float2bfloat16(v.x), h1 = __float2bfloat16(v.y);
    __nv_bfloat16 h2 = __float2bfloat16(v.z), h3 = __float2bfloat16(v.w);
    __nv_bfloat16 l0 = __float2bfloat16(v.x - __bfloat162float(h0));
    __nv_bfloat16 l1 = __float2bfloat16(v.y - __bfloat162float(h1));
    __nv_bfloat16 l2 = __float2bfloat16(v.z - __bfloat162float(h2));
    __nv_bfloat16 l3 = __float2bfloat16(v.w - __bfloat162float(h3));
    __nv_bfloat162 ph0; ph0.x = h0; ph0.y = h1;
    __nv_bfloat162 ph1; ph1.x = h2; ph1.y = h3;
    __nv_bfloat162 pl0; pl0.x = l0; pl0.y = l1;
    __nv_bfloat162 pl1; pl1.x = l2; pl1.y = l3;
    uint2 uh, ul;
    uh.x = *reinterpret_cast<unsigned*>(&ph0); uh.y = *reinterpret_cast<unsigned*>(&ph1);
    ul.x = *reinterpret_cast<unsigned*>(&pl0); ul.y = *reinterpret_cast<unsigned*>(&pl1);
    __nv_bfloat16* hb = which ? g_Wh : g_Ah;
    __nv_bfloat16* lb = which ? g_Wl : g_Al;
    reinterpret_cast<uint2*>(hb + elem_off)[i] = uh;
    reinterpret_cast<uint2*>(lb + elem_off)[i] = ul;
}

/* ---------------- HMMA 3-pass split GEMM + exp-sum epilogue ---------------- */
/* stage: [Ah 16K][Al 16K][Bh 16K][Bl 16K] = 64KB, double-buffered = 128KB */
#define STG 65536u
__global__ void __launch_bounds__(256) gemm_lse(const float* __restrict__ bp,
                                                const float* __restrict__ br)
{
    extern __shared__ char sm[];
    const uint32_t sb = smem_u32(sm);
    const int tid  = threadIdx.x;
    const int wid  = tid >> 5, lane = tid & 31;
    const int wy   = wid >> 2;          /* 0..1 : m-offset wy*64 */
    const int wx   = wid & 3;           /* 0..3 : n-offset wx*32 */

    const int mt    = blockIdx.x;       /* m fastest -> W reuse in L2 */
    const int combo = mt >> 3;
    const int m0    = (mt & 7) * MT;
    const int n0    = blockIdx.y * NT;
    const float* bias = (combo < 2) ? bp : br;

    const size_t aoff = (size_t)(combo * ROWS + m0) * H_;
    const size_t boff = ((size_t)(combo >> 1) * V_ + n0) * H_;

    /* load tasks: each subtile 128 rows x 8 chunks(16B) = 1024; 256 thr x 4 */
    uint32_t gOff[4], sOff[4];
#pragma unroll
    for (int i = 0; i < 4; ++i) {
        int t = tid + 256 * i;
        int r = t >> 3, c = t & 7;
        gOff[i] = (uint32_t)(r * H_ + c * 8);
        sOff[i] = (uint32_t)(r * 128 + ((c ^ (r & 7)) << 4));
    }

    auto load_chunk = [&](int c) {
        const uint32_t st = sb + (uint32_t)(c & 1) * STG;
        const uint32_t koff = (uint32_t)c * KCH;
#pragma unroll
        for (int i = 0; i < 4; ++i) {
            const size_t a = aoff + gOff[i] + koff;
            const size_t b = boff + gOff[i] + koff;
            cpa16(st +         sOff[i], g_Ah + a);
            cpa16(st + 16384 + sOff[i], g_Al + a);
            cpa16(st + 32768 + sOff[i], g_Wh + b);
            cpa16(st + 49152 + sOff[i], g_Wl + b);
        }
        asm volatile("cp.async.commit_group;");
    };

    float acc[4][4][4];
#pragma unroll
    for (int i = 0; i < 4; ++i)
#pragma unroll
        for (int j = 0; j < 4; ++j)
#pragma unroll
            for (int k = 0; k < 4; ++k) acc[i][j][k] = 0.f;

    load_chunk(0);

    for (int c = 0; c < KTILES; ++c) {
        asm volatile("cp.async.wait_group 0;");
        __syncthreads();
        if (c + 1 < KTILES) load_chunk(c + 1);

        const uint32_t st = sb + (uint32_t)(c & 1) * STG;
#pragma unroll
        for (int k16 = 0; k16 < 4; ++k16) {
            const int kc8 = k16 * 2 + (lane >> 4);
            uint32_t ah[4][4], al[4][4], bh[4][2], bl[4][2];
#pragma unroll
            for (int mrep = 0; mrep < 4; ++mrep) {
                const int row = wy * 64 + mrep * 16 + (lane & 15);
                const uint32_t off = row * 128 + (((kc8 ^ (row & 7))) << 4);
                ldsm4(ah[mrep][0], ah[mrep][1], ah[mrep][2], ah[mrep][3], st + off);
                ldsm4(al[mrep][0], al[mrep][1], al[mrep][2], al[mrep][3], st + 16384 + off);
            }
#pragma unroll
            for (int nh = 0; nh < 2; ++nh) {
                const int row = wx * 32 + nh * 16 + (lane & 15);
                const uint32_t off = row * 128 + (((kc8 ^ (row & 7))) << 4);
                uint32_t r0, r1, r2, r3;
                ldsm4(r0, r1, r2, r3, st + 32768 + off);
                bh[nh * 2 + 0][0] = r0; bh[nh * 2 + 0][1] = r2;
                bh[nh * 2 + 1][0] = r1; bh[nh * 2 + 1][1] = r3;
                ldsm4(r0, r1, r2, r3, st + 49152 + off);
                bl[nh * 2 + 0][0] = r0; bl[nh * 2 + 0][1] = r2;
                bl[nh * 2 + 1][0] = r1; bl[nh * 2 + 1][1] = r3;
            }
#pragma unroll
            for (int mrep = 0; mrep < 4; ++mrep)
#pragma unroll
                for (int nrep = 0; nrep < 4; ++nrep) {
                    mma16816(acc[mrep][nrep], ah[mrep], bh[nrep]);   /* ah*wh */
                    mma16816(acc[mrep][nrep], ah[mrep], bl[nrep]);   /* ah*wl */
                    mma16816(acc[mrep][nrep], al[mrep], bh[nrep]);   /* al*wh */
                }
        }
        __syncthreads();
    }

    /* ---- epilogue: per-row sum of exp(logit + bias) ---- */
    const int g = lane >> 2, q = lane & 3;
    float b0[4], b1[4];
#pragma unroll
    for (int nrep = 0; nrep < 4; ++nrep) {
        const int col = n0 + wx * 32 + nrep * 8 + q * 2;
        b0[nrep] = __ldg(&bias[col]);
        b1[nrep] = __ldg(&bias[col + 1]);
    }

    float* redf = (float*)sm;
#pragma unroll
    for (int mrep = 0; mrep < 4; ++mrep) {
        float s0 = 0.f, s1 = 0.f;
#pragma unroll
        for (int nrep = 0; nrep < 4; ++nrep) {
            s0 += expf(acc[mrep][nrep][0] + b0[nrep]) + expf(acc[mrep][nrep][1] + b1[nrep]);
            s1 += expf(acc[mrep][nrep][2] + b0[nrep]) + expf(acc[mrep][nrep][3] + b1[nrep]);
        }
        s0 += __shfl_xor_sync(0xFFFFFFFF, s0, 1);
        s0 += __shfl_xor_sync(0xFFFFFFFF, s0, 2);
        s1 += __shfl_xor_sync(0xFFFFFFFF, s1, 1);
        s1 += __shfl_xor_sync(0xFFFFFFFF, s1, 2);
        if (q == 0) {
            redf[(wy * 64 + mrep * 16 + g)     * 4 + wx] = s0;
            redf[(wy * 64 + mrep * 16 + 8 + g) * 4 + wx] = s1;
        }
    }
    __syncthreads();
    if (tid < 128) {
        const float s = redf[tid * 4] + redf[tid * 4 + 1] + redf[tid * 4 + 2] + redf[tid * 4 + 3];
        g_partial[(size_t)(combo * ROWS + m0 + tid) * NCHUNK + blockIdx.y] = s;
    }
}

/* ---------------- exact fp32 target logits (one warp per row) ---------------- */
__global__ void tgt_logits(const float* __restrict__ xc,  const float* __restrict__ xr,
                           const float* __restrict__ rxc, const float* __restrict__ rxr,
                           const float* __restrict__ Wp,  const float* __restrict__ Wr,
                           const float* __restrict__ bp,  const float* __restrict__ br,
                           const int*   __restrict__ tc,  const int*   __restrict__ tr)
{
    const int gw = blockIdx.x * 8 + (threadIdx.x >> 5);   /* 0..4095 */
    const int lane = threadIdx.x & 31;
    const int combo = gw >> 10;
    const int row   = gw & 1023;
    const float* x = (combo == 0) ? xc : (combo == 1) ? xr : (combo == 2) ? rxc : rxr;
    const float* w = (combo < 2) ? Wp : Wr;
    const float* b = (combo < 2) ? bp : br;
    const int*  tg = (combo & 1) ? tr : tc;

    const int t = __ldg(&tg[row]);
    float s = 0.f;
    if (t >= 0) {
        const float* xp = x + (size_t)row * H_;
        const float* wp = w + (size_t)t * H_;
        for (int k = lane; k < H_; k += 32) s += xp[k] * wp[k];
#pragma unroll
        for (int off = 16; off > 0; off >>= 1)
            s += __shfl_xor_sync(0xFFFFFFFF, s, off);
        s += __ldg(&b[t]);
    }
    if (lane == 0) g_tgt[combo * ROWS + row] = (t >= 0) ? s : 0.f;
}

/* ---------------- per-(combo,batch) sequence log-prob (double accum) ------- */
__global__ void reduce_rows(const int* __restrict__ tc, const int* __restrict__ tr)
{
    const int cb    = blockIdx.x;          /* combo*2 + b */
    const int combo = cb >> 1;
    const int bb    = cb & 1;
    const int* tgt  = (combo & 1) ? tr : tc;

    __shared__ double sdata[256];
    double acc = 0.0;
    for (int s = threadIdx.x; s < S_; s += 256) {
        const int row = bb * S_ + s;
        const int gr  = combo * ROWS + row;
        const float* p = &g_partial[(size_t)gr * NCHUNK];
        double sum = 0.0;
        for (int j = 0; j < NCHUNK; ++j) sum += (double)p[j];
        const int t = tgt[row];
        if (t >= 0) acc += (double)g_tgt[gr] - log(sum);
    }
    sdata[threadIdx.x] = acc;
    __syncthreads();
    for (int off = 128; off > 0; off >>= 1) {
        if (threadIdx.x < off) sdata[threadIdx.x] += sdata[threadIdx.x + off];
        __syncthreads();
    }
    if (threadIdx.x == 0) g_seq[cb] = sdata[0];
}

/* ---------------- DPO scalars (double) ---------------- */
__device__ __forceinline__ double log_sigmoid_d(double z)
{
    return (z >= 0.0) ? -log1p(exp(-z)) : (z - log1p(exp(z)));
}

__global__ void finalize(float* __restrict__ out, int out_size)
{
    if (threadIdx.x != 0 || blockIdx.x != 0) return;
    double loss = 0.0, crs = 0.0, rrs = 0.0, margin = 0.0, accc = 0.0;
    for (int b = 0; b < B_; ++b) {
        const double cl  = g_seq[0 + b];
        const double rl  = g_seq[2 + b];
        const double rcl = g_seq[4 + b];
        const double rrl = g_seq[6 + b];
        const double cr = (double)BETA_ * (cl - rcl);
        const double rr = (double)BETA_ * (rl - rrl);
        const double z  = (double)BETA_ * ((cl - rl) - (rcl - rrl));
        loss   += -log_sigmoid_d(z);
        crs    += cr;
        rrs    += rr;
        margin += cr - rr;
        accc   += (cr > rr) ? 1.0 : 0.0;
    }
    const double invB = 1.0 / (double)B_;
    float vals[6] = {(float)(loss * invB), (float)(crs * invB), (float)(rrs * invB),
                     (float)(margin * invB), (float)(accc * invB), 0.f};
    for (int i = 0; i < out_size; ++i) out[i] = (i < 6) ? vals[i] : 0.f;
}

/* ---------------- launch ---------------- */
extern "C" void kernel_launch(void* const* d_in, const int* in_sizes, int n_in,
                              void* d_out, int out_size)
{
    const float* xc  = (const float*)d_in[0];
    const float* xr  = (const float*)d_in[1];
    const float* rxc = (const float*)d_in[2];
    const float* rxr = (const float*)d_in[3];
    const float* Wp  = (const float*)d_in[4];
    const float* bp  = (const float*)d_in[5];
    const float* Wr  = (const float*)d_in[6];
    const float* br  = (const float*)d_in[7];
    const int*   tc  = (const int*)d_in[8];
    const int*   tr  = (const int*)d_in[9];

    const int nA4 = ROWS * H_ / 4;                   /* 524288 */
    const int nW4 = (int)((size_t)V_ * H_ / 4);      /* 16384000 */
    split_bf16<<<(nA4 + 255) / 256, 256>>>((const float4*)xc,  0, 0 * (size_t)ROWS * H_, nA4);
    split_bf16<<<(nA4 + 255) / 256, 256>>>((const float4*)xr,  0, 1 * (size_t)ROWS * H_, nA4);
    split_bf16<<<(nA4 + 255) / 256, 256>>>((const float4*)rxc, 0, 2 * (size_t)ROWS * H_, nA4);
    split_bf16<<<(nA4 + 255) / 256, 256>>>((const float4*)rxr, 0, 3 * (size_t)ROWS * H_, nA4);
    split_bf16<<<(nW4 + 255) / 256, 256>>>((const float4*)Wp,  1, 0, nW4);
    split_bf16<<<(nW4 + 255) / 256, 256>>>((const float4*)Wr,  1, (size_t)V_ * H_, nW4);

    static const int SMEM_BYTES = 131072;
    cudaFuncSetAttribute(gemm_lse, cudaFuncAttributeMaxDynamicSharedMemorySize, SMEM_BYTES);
    dim3 gg(4 * ROWS / MT, V_ / NT);                 /* (32, 250) */
    gemm_lse<<<gg, 256, SMEM_BYTES>>>(bp, br);

    tgt_logits<<<512, 256>>>(xc, xr, rxc, rxr, Wp, Wr, bp, br, tc, tr);
    reduce_rows<<<8, 256>>>(tc, tr);
    finalize<<<1, 1>>>((float*)d_out, out_size);
}

// round 5
// speedup vs baseline: 6.3181x; 1.4421x over previous
#include <cuda_runtime.h>
#include <cuda_fp16.h>
#include <math.h>
#include <stdint.h>
#include <stddef.h>

#define B_    2
#define S_    512
#define H_    2048
#define V_    32000
#define BETA_ 0.1f

#define MT 128
#define NT 128
#define KCH 64                    /* K elems per stage chunk */
#define KTILES (H_/KCH)           /* 32 */
#define NCHUNK (V_/NT)            /* 250 */
#define ROWS  1024                /* B*S per combo */

/* ---------------- device scratch (static, allocation-free) ---------------- */
__device__ __align__(256) __half g_Af[4u * ROWS * H_];
__device__ __align__(256) __half g_Wh[2u * (size_t)V_ * H_];
__device__ __align__(256) __half g_Wl[2u * (size_t)V_ * H_];
__device__ float  g_partial[4u * ROWS * NCHUNK];
__device__ float  g_tgt[4u * ROWS];
__device__ double g_seq[8];

/* ---------------- helpers ---------------- */
__device__ __forceinline__ uint32_t smem_u32(const void* p) {
    uint32_t a;
    asm("{ .reg .u64 t; cvta.to.shared.u64 t, %1; cvt.u32.u64 %0, t; }" : "=r"(a) : "l"(p));
    return a;
}
__device__ __forceinline__ void cpa16(uint32_t dst, const void* src) {
    asm volatile("cp.async.cg.shared.global [%0], [%1], 16;" :: "r"(dst), "l"(src));
}
__device__ __forceinline__ void ldsm4(uint32_t& r0, uint32_t& r1, uint32_t& r2, uint32_t& r3,
                                      uint32_t a) {
    asm volatile("ldmatrix.sync.aligned.m8n8.x4.shared.b16 {%0,%1,%2,%3}, [%4];"
                 : "=r"(r0), "=r"(r1), "=r"(r2), "=r"(r3) : "r"(a));
}
__device__ __forceinline__ void mma16816(float* c, const uint32_t* a, const uint32_t* b) {
    asm volatile(
        "mma.sync.aligned.m16n8k16.row.col.f32.f16.f16.f32 "
        "{%0,%1,%2,%3}, {%4,%5,%6,%7}, {%8,%9}, {%0,%1,%2,%3};"
        : "+f"(c[0]), "+f"(c[1]), "+f"(c[2]), "+f"(c[3])
        : "r"(a[0]), "r"(a[1]), "r"(a[2]), "r"(a[3]), "r"(b[0]), "r"(b[1]));
}

/* ---------------- prep: A fp32 -> fp16 ---------------- */
__global__ void conv_a(const float4* __restrict__ src, size_t elem_off, int n4)
{
    int i = blockIdx.x * blockDim.x + threadIdx.x;
    if (i >= n4) return;
    float4 v = src[i];
    __half2 p0 = __floats2half2_rn(v.x, v.y);
    __half2 p1 = __floats2half2_rn(v.z, v.w);
    uint2 u;
    u.x = *reinterpret_cast<unsigned*>(&p0);
    u.y = *reinterpret_cast<unsigned*>(&p1);
    reinterpret_cast<uint2*>(g_Af + elem_off)[i] = u;
}

/* ---------------- prep: W fp32 -> fp16 hi/lo split ---------------- */
__global__ void split_w(const float4* __restrict__ src, size_t elem_off, int n4)
{
    int i = blockIdx.x * blockDim.x + threadIdx.x;
    if (i >= n4) return;
    float4 v = src[i];
    __half h0 = __float2half_rn(v.x), h1 = __float2half_rn(v.y);
    __half h2 = __float2half_rn(v.z), h3 = __float2half_rn(v.w);
    __half l0 = __float2half_rn(v.x - __half2float(h0));
    __half l1 = __float2half_rn(v.y - __half2float(h1));
    __half l2 = __float2half_rn(v.z - __half2float(h2));
    __half l3 = __float2half_rn(v.w - __half2float(h3));
    __half2 ph0; ph0.x = h0; ph0.y = h1;
    __half2 ph1; ph1.x = h2; ph1.y = h3;
    __half2 pl0; pl0.x = l0; pl0.y = l1;
    __half2 pl1; pl1.x = l2; pl1.y = l3;
    uint2 uh, ul;
    uh.x = *reinterpret_cast<unsigned*>(&ph0); uh.y = *reinterpret_cast<unsigned*>(&ph1);
    ul.x = *reinterpret_cast<unsigned*>(&pl0); ul.y = *reinterpret_cast<unsigned*>(&pl1);
    reinterpret_cast<uint2*>(g_Wh + elem_off)[i] = uh;
    reinterpret_cast<uint2*>(g_Wl + elem_off)[i] = ul;
}

/* ---------------- HMMA 2-pass GEMM + exp-sum epilogue ---------------- */
/* stage: [A 16K][Bh 16K][Bl 16K] = 48KB, 3 stages = 144KB */
#define STG 49152u
__global__ void __launch_bounds__(256, 1) gemm_lse(const float* __restrict__ bp,
                                                   const float* __restrict__ br)
{
    extern __shared__ char sm[];
    const uint32_t sb = smem_u32(sm);
    const int tid  = threadIdx.x;
    const int wid  = tid >> 5, lane = tid & 31;
    const int wy   = wid >> 2;          /* 0..1 : m-offset wy*64 */
    const int wx   = wid & 3;           /* 0..3 : n-offset wx*32 */

    const int mt    = blockIdx.x;       /* m fastest -> W reuse in L2 */
    const int combo = mt >> 3;
    const int m0    = (mt & 7) * MT;
    const int n0    = blockIdx.y * NT;
    const float* bias = (combo < 2) ? bp : br;

    const size_t aoff = (size_t)(combo * ROWS + m0) * H_;
    const size_t boff = ((size_t)(combo >> 1) * V_ + n0) * H_;

    /* load tasks: each subtile 128 rows x 8 chunks(16B) = 1024 vec; 256 thr x 4 */
    uint32_t gOff[4], sOff[4];
#pragma unroll
    for (int i = 0; i < 4; ++i) {
        int t = tid + 256 * i;
        int r = t >> 3, c = t & 7;
        gOff[i] = (uint32_t)(r * H_ + c * 8);
        sOff[i] = (uint32_t)(r * 128 + ((c ^ (r & 7)) << 4));
    }

    auto load_chunk = [&](int c) {
        const uint32_t st = sb + (uint32_t)(c % 3) * STG;
        const uint32_t koff = (uint32_t)c * KCH;
#pragma unroll
        for (int i = 0; i < 4; ++i) {
            const size_t a = aoff + gOff[i] + koff;
            const size_t b = boff + gOff[i] + koff;
            cpa16(st +         sOff[i], g_Af + a);
            cpa16(st + 16384 + sOff[i], g_Wh + b);
            cpa16(st + 32768 + sOff[i], g_Wl + b);
        }
        asm volatile("cp.async.commit_group;");
    };

    float acc[4][4][4];
#pragma unroll
    for (int i = 0; i < 4; ++i)
#pragma unroll
        for (int j = 0; j < 4; ++j)
#pragma unroll
            for (int k = 0; k < 4; ++k) acc[i][j][k] = 0.f;

    load_chunk(0);
    load_chunk(1);

    for (int c = 0; c < KTILES; ++c) {
        if (c + 1 < KTILES) asm volatile("cp.async.wait_group 1;");
        else                asm volatile("cp.async.wait_group 0;");
        __syncthreads();                   /* data(c) visible; compute(c-1) done */
        if (c + 2 < KTILES) load_chunk(c + 2);   /* overwrites stage (c-1)%3 */

        const uint32_t st = sb + (uint32_t)(c % 3) * STG;
#pragma unroll
        for (int k16 = 0; k16 < 4; ++k16) {
            const int kc8 = k16 * 2 + (lane >> 4);
            uint32_t a[4][4], bh[4][2], bl[4][2];
#pragma unroll
            for (int mrep = 0; mrep < 4; ++mrep) {
                const int row = wy * 64 + mrep * 16 + (lane & 15);
                const uint32_t off = row * 128 + (((kc8 ^ (row & 7))) << 4);
                ldsm4(a[mrep][0], a[mrep][1], a[mrep][2], a[mrep][3], st + off);
            }
#pragma unroll
            for (int nh = 0; nh < 2; ++nh) {
                const int row = wx * 32 + nh * 16 + (lane & 15);
                const uint32_t off = row * 128 + (((kc8 ^ (row & 7))) << 4);
                uint32_t r0, r1, r2, r3;
                ldsm4(r0, r1, r2, r3, st + 16384 + off);
                bh[nh * 2 + 0][0] = r0; bh[nh * 2 + 0][1] = r2;
                bh[nh * 2 + 1][0] = r1; bh[nh * 2 + 1][1] = r3;
                ldsm4(r0, r1, r2, r3, st + 32768 + off);
                bl[nh * 2 + 0][0] = r0; bl[nh * 2 + 0][1] = r2;
                bl[nh * 2 + 1][0] = r1; bl[nh * 2 + 1][1] = r3;
            }
#pragma unroll
            for (int mrep = 0; mrep < 4; ++mrep)
#pragma unroll
                for (int nrep = 0; nrep < 4; ++nrep) {
                    mma16816(acc[mrep][nrep], a[mrep], bh[nrep]);   /* a*wh */
                    mma16816(acc[mrep][nrep], a[mrep], bl[nrep]);   /* a*wl */
                }
        }
        __syncthreads();   /* all warps done with stage (c%3) before reuse */
    }

    /* ---- epilogue: per-row sum of exp(logit + bias) ---- */
    const int g = lane >> 2, q = lane & 3;
    float b0[4], b1[4];
#pragma unroll
    for (int nrep = 0; nrep < 4; ++nrep) {
        const int col = n0 + wx * 32 + nrep * 8 + q * 2;
        b0[nrep] = __ldg(&bias[col]);
        b1[nrep] = __ldg(&bias[col + 1]);
    }

    float* redf = (float*)sm;
#pragma unroll
    for (int mrep = 0; mrep < 4; ++mrep) {
        float s0 = 0.f, s1 = 0.f;
#pragma unroll
        for (int nrep = 0; nrep < 4; ++nrep) {
            s0 += expf(acc[mrep][nrep][0] + b0[nrep]) + expf(acc[mrep][nrep][1] + b1[nrep]);
            s1 += expf(acc[mrep][nrep][2] + b0[nrep]) + expf(acc[mrep][nrep][3] + b1[nrep]);
        }
        s0 += __shfl_xor_sync(0xFFFFFFFF, s0, 1);
        s0 += __shfl_xor_sync(0xFFFFFFFF, s0, 2);
        s1 += __shfl_xor_sync(0xFFFFFFFF, s1, 1);
        s1 += __shfl_xor_sync(0xFFFFFFFF, s1, 2);
        if (q == 0) {
            redf[(wy * 64 + mrep * 16 + g)     * 4 + wx] = s0;
            redf[(wy * 64 + mrep * 16 + 8 + g) * 4 + wx] = s1;
        }
    }
    __syncthreads();
    if (tid < 128) {
        const float s = redf[tid * 4] + redf[tid * 4 + 1] + redf[tid * 4 + 2] + redf[tid * 4 + 3];
        g_partial[(size_t)(combo * ROWS + m0 + tid) * NCHUNK + blockIdx.y] = s;
    }
}

/* ---------------- exact fp32 target logits (one warp per row) ---------------- */
__global__ void tgt_logits(const float* __restrict__ xc,  const float* __restrict__ xr,
                           const float* __restrict__ rxc, const float* __restrict__ rxr,
                           const float* __restrict__ Wp,  const float* __restrict__ Wr,
                           const float* __restrict__ bp,  const float* __restrict__ br,
                           const int*   __restrict__ tc,  const int*   __restrict__ tr)
{
    const int gw = blockIdx.x * 8 + (threadIdx.x >> 5);   /* 0..4095 */
    const int lane = threadIdx.x & 31;
    const int combo = gw >> 10;
    const int row   = gw & 1023;
    const float* x = (combo == 0) ? xc : (combo == 1) ? xr : (combo == 2) ? rxc : rxr;
    const float* w = (combo < 2) ? Wp : Wr;
    const float* b = (combo < 2) ? bp : br;
    const int*  tg = (combo & 1) ? tr : tc;

    const int t = __ldg(&tg[row]);
    float s = 0.f;
    if (t >= 0) {
        const float* xp = x + (size_t)row * H_;
        const float* wp = w + (size_t)t * H_;
        for (int k = lane; k < H_; k += 32) s += xp[k] * wp[k];
#pragma unroll
        for (int off = 16; off > 0; off >>= 1)
            s += __shfl_xor_sync(0xFFFFFFFF, s, off);
        s += __ldg(&b[t]);
    }
    if (lane == 0) g_tgt[combo * ROWS + row] = (t >= 0) ? s : 0.f;
}

/* ---------------- per-(combo,batch) sequence log-prob (double accum) ------- */
__global__ void reduce_rows(const int* __restrict__ tc, const int* __restrict__ tr)
{
    const int cb    = blockIdx.x;          /* combo*2 + b */
    const int combo = cb >> 1;
    const int bb    = cb & 1;
    const int* tgt  = (combo & 1) ? tr : tc;

    __shared__ double sdata[256];
    double acc = 0.0;
    for (int s = threadIdx.x; s < S_; s += 256) {
        const int row = bb * S_ + s;
        const int gr  = combo * ROWS + row;
        const float* p = &g_partial[(size_t)gr * NCHUNK];
        double sum = 0.0;
        for (int j = 0; j < NCHUNK; ++j) sum += (double)p[j];
        const int t = tgt[row];
        if (t >= 0) acc += (double)g_tgt[gr] - log(sum);
    }
    sdata[threadIdx.x] = acc;
    __syncthreads();
    for (int off = 128; off > 0; off >>= 1) {
        if (threadIdx.x < off) sdata[threadIdx.x] += sdata[threadIdx.x + off];
        __syncthreads();
    }
    if (threadIdx.x == 0) g_seq[cb] = sdata[0];
}

/* ---------------- DPO scalars (double) ---------------- */
__device__ __forceinline__ double log_sigmoid_d(double z)
{
    return (z >= 0.0) ? -log1p(exp(-z)) : (z - log1p(exp(z)));
}

__global__ void finalize(float* __restrict__ out, int out_size)
{
    if (threadIdx.x != 0 || blockIdx.x != 0) return;
    double loss = 0.0, crs = 0.0, rrs = 0.0, margin = 0.0, accc = 0.0;
    for (int b = 0; b < B_; ++b) {
        const double cl  = g_seq[0 + b];
        const double rl  = g_seq[2 + b];
        const double rcl = g_seq[4 + b];
        const double rrl = g_seq[6 + b];
        const double cr = (double)BETA_ * (cl - rcl);
        const double rr = (double)BETA_ * (rl - rrl);
        const double z  = (double)BETA_ * ((cl - rl) - (rcl - rrl));
        loss   += -log_sigmoid_d(z);
        crs    += cr;
        rrs    += rr;
        margin += cr - rr;
        accc   += (cr > rr) ? 1.0 : 0.0;
    }
    const double invB = 1.0 / (double)B_;
    float vals[6] = {(float)(loss * invB), (float)(crs * invB), (float)(rrs * invB),
                     (float)(margin * invB), (float)(accc * invB), 0.f};
    for (int i = 0; i < out_size; ++i) out[i] = (i < 6) ? vals[i] : 0.f;
}

/* ---------------- launch ---------------- */
extern "C" void kernel_launch(void* const* d_in, const int* in_sizes, int n_in,
                              void* d_out, int out_size)
{
    const float* xc  = (const float*)d_in[0];
    const float* xr  = (const float*)d_in[1];
    const float* rxc = (const float*)d_in[2];
    const float* rxr = (const float*)d_in[3];
    const float* Wp  = (const float*)d_in[4];
    const float* bp  = (const float*)d_in[5];
    const float* Wr  = (const float*)d_in[6];
    const float* br  = (const float*)d_in[7];
    const int*   tc  = (const int*)d_in[8];
    const int*   tr  = (const int*)d_in[9];

    const int nA4 = ROWS * H_ / 4;                   /* 524288 */
    const int nW4 = (int)((size_t)V_ * H_ / 4);      /* 16384000 */
    conv_a<<<(nA4 + 255) / 256, 256>>>((const float4*)xc,  0 * (size_t)ROWS * H_, nA4);
    conv_a<<<(nA4 + 255) / 256, 256>>>((const float4*)xr,  1 * (size_t)ROWS * H_, nA4);
    conv_a<<<(nA4 + 255) / 256, 256>>>((const float4*)rxc, 2 * (size_t)ROWS * H_, nA4);
    conv_a<<<(nA4 + 255) / 256, 256>>>((const float4*)rxr, 3 * (size_t)ROWS * H_, nA4);
    split_w<<<(nW4 + 255) / 256, 256>>>((const float4*)Wp, 0, nW4);
    split_w<<<(nW4 + 255) / 256, 256>>>((const float4*)Wr, (size_t)V_ * H_, nW4);

    static const int SMEM_BYTES = 3 * 49152;         /* 147456 */
    cudaFuncSetAttribute(gemm_lse, cudaFuncAttributeMaxDynamicSharedMemorySize, SMEM_BYTES);
    dim3 gg(4 * ROWS / MT, V_ / NT);                 /* (32, 250) */
    gemm_lse<<<gg, 256, SMEM_BYTES>>>(bp, br);

    tgt_logits<<<512, 256>>>(xc, xr, rxc, rxr, Wp, Wr, bp, br, tc, tr);
    reduce_rows<<<8, 256>>>(tc, tr);
    finalize<<<1, 1>>>((float*)d_out, out_size);
}

// round 6
// speedup vs baseline: 7.2702x; 1.1507x over previous
#include <cuda_runtime.h>
#include <cuda_fp16.h>
#include <math.h>
#include <stdint.h>
#include <stddef.h>

#define B_    2
#define S_    512
#define H_    2048
#define V_    32000
#define BETA_ 0.1f

#define MT 128
#define NT 128
#define KCH 64                    /* K elems per stage chunk */
#define KTILES (H_/KCH)           /* 32 */
#define NCHUNK (V_/NT)            /* 250 */
#define ROWS  1024                /* B*S per combo */

/* ---------------- device scratch (static, allocation-free) ---------------- */
__device__ __align__(256) __half g_Af[4u * ROWS * H_];
__device__ __align__(256) __half g_Wh[2u * (size_t)V_ * H_];
__device__ __align__(256) __half g_Wl[2u * (size_t)V_ * H_];
__device__ float  g_partial[4u * ROWS * NCHUNK];
__device__ float  g_tgt[4u * ROWS];
__device__ double g_seq[8];

/* ---------------- helpers ---------------- */
__device__ __forceinline__ uint32_t smem_u32(const void* p) {
    uint32_t a;
    asm("{ .reg .u64 t; cvta.to.shared.u64 t, %1; cvt.u32.u64 %0, t; }" : "=r"(a) : "l"(p));
    return a;
}
__device__ __forceinline__ void cpa16(uint32_t dst, const void* src) {
    asm volatile("cp.async.cg.shared.global [%0], [%1], 16;" :: "r"(dst), "l"(src));
}
__device__ __forceinline__ void ldsm4(uint32_t& r0, uint32_t& r1, uint32_t& r2, uint32_t& r3,
                                      uint32_t a) {
    asm volatile("ldmatrix.sync.aligned.m8n8.x4.shared.b16 {%0,%1,%2,%3}, [%4];"
                 : "=r"(r0), "=r"(r1), "=r"(r2), "=r"(r3) : "r"(a));
}
__device__ __forceinline__ void mma16816(float* c, const uint32_t* a, const uint32_t* b) {
    asm volatile(
        "mma.sync.aligned.m16n8k16.row.col.f32.f16.f16.f32 "
        "{%0,%1,%2,%3}, {%4,%5,%6,%7}, {%8,%9}, {%0,%1,%2,%3};"
        : "+f"(c[0]), "+f"(c[1]), "+f"(c[2]), "+f"(c[3])
        : "r"(a[0]), "r"(a[1]), "r"(a[2]), "r"(a[3]), "r"(b[0]), "r"(b[1]));
}

/* ---------------- prep: A fp32 -> fp16 ---------------- */
__global__ void conv_a(const float4* __restrict__ src, size_t elem_off, int n4)
{
    int i = blockIdx.x * blockDim.x + threadIdx.x;
    if (i >= n4) return;
    float4 v = src[i];
    __half2 p0 = __floats2half2_rn(v.x, v.y);
    __half2 p1 = __floats2half2_rn(v.z, v.w);
    uint2 u;
    u.x = *reinterpret_cast<unsigned*>(&p0);
    u.y = *reinterpret_cast<unsigned*>(&p1);
    reinterpret_cast<uint2*>(g_Af + elem_off)[i] = u;
}

/* ---------------- prep: W fp32 -> fp16 hi/lo split ---------------- */
__global__ void split_w(const float4* __restrict__ src, size_t elem_off, int n4)
{
    int i = blockIdx.x * blockDim.x + threadIdx.x;
    if (i >= n4) return;
    float4 v = src[i];
    __half h0 = __float2half_rn(v.x), h1 = __float2half_rn(v.y);
    __half h2 = __float2half_rn(v.z), h3 = __float2half_rn(v.w);
    __half l0 = __float2half_rn(v.x - __half2float(h0));
    __half l1 = __float2half_rn(v.y - __half2float(h1));
    __half l2 = __float2half_rn(v.z - __half2float(h2));
    __half l3 = __float2half_rn(v.w - __half2float(h3));
    __half2 ph0; ph0.x = h0; ph0.y = h1;
    __half2 ph1; ph1.x = h2; ph1.y = h3;
    __half2 pl0; pl0.x = l0; pl0.y = l1;
    __half2 pl1; pl1.x = l2; pl1.y = l3;
    uint2 uh, ul;
    uh.x = *reinterpret_cast<unsigned*>(&ph0); uh.y = *reinterpret_cast<unsigned*>(&ph1);
    ul.x = *reinterpret_cast<unsigned*>(&pl0); ul.y = *reinterpret_cast<unsigned*>(&pl1);
    reinterpret_cast<uint2*>(g_Wh + elem_off)[i] = uh;
    reinterpret_cast<uint2*>(g_Wl + elem_off)[i] = ul;
}

/* ---------------- HMMA 2-pass GEMM + exp-sum epilogue ---------------- */
/* stage: [A 16K][Bh 16K][Bl 16K] = 48KB, 2 stages = 96KB, 2 CTAs/SM */
#define STG 49152u
__global__ void __launch_bounds__(256, 2) gemm_lse(const float* __restrict__ bp,
                                                   const float* __restrict__ br)
{
    extern __shared__ char sm[];
    const uint32_t sb = smem_u32(sm);
    const int tid  = threadIdx.x;
    const int wid  = tid >> 5, lane = tid & 31;
    const int wy   = wid >> 2;          /* 0..1 : m-offset wy*64 */
    const int wx   = wid & 3;           /* 0..3 : n-offset wx*32 */

    const int mt    = blockIdx.x;       /* m fastest -> W reuse in L2 */
    const int combo = mt >> 3;
    const int m0    = (mt & 7) * MT;
    const int n0    = blockIdx.y * NT;
    const float* bias = (combo < 2) ? bp : br;

    const size_t aoff = (size_t)(combo * ROWS + m0) * H_;
    const size_t boff = ((size_t)(combo >> 1) * V_ + n0) * H_;

    /* load tasks: each subtile 128 rows x 8 chunks(16B) = 1024 vec; 256 thr x 4 */
    uint32_t gOff[4], sOff[4];
#pragma unroll
    for (int i = 0; i < 4; ++i) {
        int t = tid + 256 * i;
        int r = t >> 3, c = t & 7;
        gOff[i] = (uint32_t)(r * H_ + c * 8);
        sOff[i] = (uint32_t)(r * 128 + ((c ^ (r & 7)) << 4));
    }

    auto load_chunk = [&](int c) {
        const uint32_t st = sb + (uint32_t)(c & 1) * STG;
        const uint32_t koff = (uint32_t)c * KCH;
#pragma unroll
        for (int i = 0; i < 4; ++i) {
            const size_t a = aoff + gOff[i] + koff;
            const size_t b = boff + gOff[i] + koff;
            cpa16(st +         sOff[i], g_Af + a);
            cpa16(st + 16384 + sOff[i], g_Wh + b);
            cpa16(st + 32768 + sOff[i], g_Wl + b);
        }
        asm volatile("cp.async.commit_group;");
    };

    float acc[4][4][4];
#pragma unroll
    for (int i = 0; i < 4; ++i)
#pragma unroll
        for (int j = 0; j < 4; ++j)
#pragma unroll
            for (int k = 0; k < 4; ++k) acc[i][j][k] = 0.f;

    load_chunk(0);

    for (int c = 0; c < KTILES; ++c) {
        asm volatile("cp.async.wait_group 0;");
        __syncthreads();                   /* data(c) visible; compute(c-1) done */
        if (c + 1 < KTILES) load_chunk(c + 1);   /* fills other stage during compute */

        const uint32_t st = sb + (uint32_t)(c & 1) * STG;
#pragma unroll
        for (int k16 = 0; k16 < 4; ++k16) {
            const int kc8 = k16 * 2 + (lane >> 4);
            uint32_t a[4][4];
#pragma unroll
            for (int mrep = 0; mrep < 4; ++mrep) {
                const int row = wy * 64 + mrep * 16 + (lane & 15);
                const uint32_t off = row * 128 + (((kc8 ^ (row & 7))) << 4);
                ldsm4(a[mrep][0], a[mrep][1], a[mrep][2], a[mrep][3], st + off);
            }
#pragma unroll
            for (int nh = 0; nh < 2; ++nh) {   /* n-halves keep b-frag regs low */
                const int row = wx * 32 + nh * 16 + (lane & 15);
                const uint32_t off = row * 128 + (((kc8 ^ (row & 7))) << 4);
                uint32_t bh[2][2], bl[2][2];
                uint32_t r0, r1, r2, r3;
                ldsm4(r0, r1, r2, r3, st + 16384 + off);
                bh[0][0] = r0; bh[0][1] = r2;
                bh[1][0] = r1; bh[1][1] = r3;
                ldsm4(r0, r1, r2, r3, st + 32768 + off);
                bl[0][0] = r0; bl[0][1] = r2;
                bl[1][0] = r1; bl[1][1] = r3;
#pragma unroll
                for (int mrep = 0; mrep < 4; ++mrep)
#pragma unroll
                    for (int nr = 0; nr < 2; ++nr) {
                        mma16816(acc[mrep][nh * 2 + nr], a[mrep], bh[nr]);  /* a*wh */
                        mma16816(acc[mrep][nh * 2 + nr], a[mrep], bl[nr]);  /* a*wl */
                    }
            }
        }
        /* no bottom sync: next-iter wait+sync protects stage reuse */
    }

    /* ---- epilogue: per-row sum of exp(logit + bias) ---- */
    const int g = lane >> 2, q = lane & 3;
    float b0[4], b1[4];
#pragma unroll
    for (int nrep = 0; nrep < 4; ++nrep) {
        const int col = n0 + wx * 32 + nrep * 8 + q * 2;
        b0[nrep] = __ldg(&bias[col]);
        b1[nrep] = __ldg(&bias[col + 1]);
    }

    /* redf lives in stage-0 area (last compute used stage 1: 31&1==1) */
    float* redf = (float*)sm;
#pragma unroll
    for (int mrep = 0; mrep < 4; ++mrep) {
        float s0 = 0.f, s1 = 0.f;
#pragma unroll
        for (int nrep = 0; nrep < 4; ++nrep) {
            s0 += expf(acc[mrep][nrep][0] + b0[nrep]) + expf(acc[mrep][nrep][1] + b1[nrep]);
            s1 += expf(acc[mrep][nrep][2] + b0[nrep]) + expf(acc[mrep][nrep][3] + b1[nrep]);
        }
        s0 += __shfl_xor_sync(0xFFFFFFFF, s0, 1);
        s0 += __shfl_xor_sync(0xFFFFFFFF, s0, 2);
        s1 += __shfl_xor_sync(0xFFFFFFFF, s1, 1);
        s1 += __shfl_xor_sync(0xFFFFFFFF, s1, 2);
        if (q == 0) {
            redf[(wy * 64 + mrep * 16 + g)     * 4 + wx] = s0;
            redf[(wy * 64 + mrep * 16 + 8 + g) * 4 + wx] = s1;
        }
    }
    __syncthreads();
    if (tid < 128) {
        const float s = redf[tid * 4] + redf[tid * 4 + 1] + redf[tid * 4 + 2] + redf[tid * 4 + 3];
        g_partial[(size_t)(combo * ROWS + m0 + tid) * NCHUNK + blockIdx.y] = s;
    }
}

/* ---------------- exact fp32 target logits (one warp per row) ---------------- */
__global__ void tgt_logits(const float* __restrict__ xc,  const float* __restrict__ xr,
                           const float* __restrict__ rxc, const float* __restrict__ rxr,
                           const float* __restrict__ Wp,  const float* __restrict__ Wr,
                           const float* __restrict__ bp,  const float* __restrict__ br,
                           const int*   __restrict__ tc,  const int*   __restrict__ tr)
{
    const int gw = blockIdx.x * 8 + (threadIdx.x >> 5);   /* 0..4095 */
    const int lane = threadIdx.x & 31;
    const int combo = gw >> 10;
    const int row   = gw & 1023;
    const float* x = (combo == 0) ? xc : (combo == 1) ? xr : (combo == 2) ? rxc : rxr;
    const float* w = (combo < 2) ? Wp : Wr;
    const float* b = (combo < 2) ? bp : br;
    const int*  tg = (combo & 1) ? tr : tc;

    const int t = __ldg(&tg[row]);
    float s = 0.f;
    if (t >= 0) {
        const float* xp = x + (size_t)row * H_;
        const float* wp = w + (size_t)t * H_;
        for (int k = lane; k < H_; k += 32) s += xp[k] * wp[k];
#pragma unroll
        for (int off = 16; off > 0; off >>= 1)
            s += __shfl_xor_sync(0xFFFFFFFF, s, off);
        s += __ldg(&b[t]);
    }
    if (lane == 0) g_tgt[combo * ROWS + row] = (t >= 0) ? s : 0.f;
}

/* ---------------- per-(combo,batch) sequence log-prob (double accum) ------- */
__global__ void reduce_rows(const int* __restrict__ tc, const int* __restrict__ tr)
{
    const int cb    = blockIdx.x;          /* combo*2 + b */
    const int combo = cb >> 1;
    const int bb    = cb & 1;
    const int* tgt  = (combo & 1) ? tr : tc;

    __shared__ double sdata[256];
    double acc = 0.0;
    for (int s = threadIdx.x; s < S_; s += 256) {
        const int row = bb * S_ + s;
        const int gr  = combo * ROWS + row;
        const float* p = &g_partial[(size_t)gr * NCHUNK];
        double sum = 0.0;
        for (int j = 0; j < NCHUNK; ++j) sum += (double)p[j];
        const int t = tgt[row];
        if (t >= 0) acc += (double)g_tgt[gr] - log(sum);
    }
    sdata[threadIdx.x] = acc;
    __syncthreads();
    for (int off = 128; off > 0; off >>= 1) {
        if (threadIdx.x < off) sdata[threadIdx.x] += sdata[threadIdx.x + off];
        __syncthreads();
    }
    if (threadIdx.x == 0) g_seq[cb] = sdata[0];
}

/* ---------------- DPO scalars (double) ---------------- */
__device__ __forceinline__ double log_sigmoid_d(double z)
{
    return (z >= 0.0) ? -log1p(exp(-z)) : (z - log1p(exp(z)));
}

__global__ void finalize(float* __restrict__ out, int out_size)
{
    if (threadIdx.x != 0 || blockIdx.x != 0) return;
    double loss = 0.0, crs = 0.0, rrs = 0.0, margin = 0.0, accc = 0.0;
    for (int b = 0; b < B_; ++b) {
        const double cl  = g_seq[0 + b];
        const double rl  = g_seq[2 + b];
        const double rcl = g_seq[4 + b];
        const double rrl = g_seq[6 + b];
        const double cr = (double)BETA_ * (cl - rcl);
        const double rr = (double)BETA_ * (rl - rrl);
        const double z  = (double)BETA_ * ((cl - rl) - (rcl - rrl));
        loss   += -log_sigmoid_d(z);
        crs    += cr;
        rrs    += rr;
        margin += cr - rr;
        accc   += (cr > rr) ? 1.0 : 0.0;
    }
    const double invB = 1.0 / (double)B_;
    float vals[6] = {(float)(loss * invB), (float)(crs * invB), (float)(rrs * invB),
                     (float)(margin * invB), (float)(accc * invB), 0.f};
    for (int i = 0; i < out_size; ++i) out[i] = (i < 6) ? vals[i] : 0.f;
}

/* ---------------- launch ---------------- */
extern "C" void kernel_launch(void* const* d_in, const int* in_sizes, int n_in,
                              void* d_out, int out_size)
{
    const float* xc  = (const float*)d_in[0];
    const float* xr  = (const float*)d_in[1];
    const float* rxc = (const float*)d_in[2];
    const float* rxr = (const float*)d_in[3];
    const float* Wp  = (const float*)d_in[4];
    const float* bp  = (const float*)d_in[5];
    const float* Wr  = (const float*)d_in[6];
    const float* br  = (const float*)d_in[7];
    const int*   tc  = (const int*)d_in[8];
    const int*   tr  = (const int*)d_in[9];

    const int nA4 = ROWS * H_ / 4;                   /* 524288 */
    const int nW4 = (int)((size_t)V_ * H_ / 4);      /* 16384000 */
    conv_a<<<(nA4 + 255) / 256, 256>>>((const float4*)xc,  0 * (size_t)ROWS * H_, nA4);
    conv_a<<<(nA4 + 255) / 256, 256>>>((const float4*)xr,  1 * (size_t)ROWS * H_, nA4);
    conv_a<<<(nA4 + 255) / 256, 256>>>((const float4*)rxc, 2 * (size_t)ROWS * H_, nA4);
    conv_a<<<(nA4 + 255) / 256, 256>>>((const float4*)rxr, 3 * (size_t)ROWS * H_, nA4);
    split_w<<<(nW4 + 255) / 256, 256>>>((const float4*)Wp, 0, nW4);
    split_w<<<(nW4 + 255) / 256, 256>>>((const float4*)Wr, (size_t)V_ * H_, nW4);

    static const int SMEM_BYTES = 2 * 49152;         /* 98304 per CTA */
    cudaFuncSetAttribute(gemm_lse, cudaFuncAttributeMaxDynamicSharedMemorySize, SMEM_BYTES);
    dim3 gg(4 * ROWS / MT, V_ / NT);                 /* (32, 250) */
    gemm_lse<<<gg, 256, SMEM_BYTES>>>(bp, br);

    tgt_logits<<<512, 256>>>(xc, xr, rxc, rxr, Wp, Wr, bp, br, tc, tr);
    reduce_rows<<<8, 256>>>(tc, tr);
    finalize<<<1, 1>>>((float*)d_out, out_size);
}

// round 8
// speedup vs baseline: 12.9663x; 1.7835x over previous
#include <cuda_runtime.h>
#include <cuda_fp16.h>
#include <math.h>
#include <stdint.h>
#include <stddef.h>

#define B_    2
#define S_    512
#define H_    2048
#define V_    32000
#define BETA_ 0.1f

#define MT 128
#define NT 128
#define KCH 64                    /* K elems per stage chunk */
#define KTILES (H_/KCH)           /* 32 */
#define NCHUNK (V_/NT)            /* 250 */
#define ROWS  1024                /* B*S per combo */

/* ---------------- device scratch (static, allocation-free) ---------------- */
__device__ __align__(256) __half g_Af[4u * ROWS * H_];
__device__ __align__(256) __half g_Wf[2u * (size_t)V_ * H_];
__device__ float  g_partial[4u * ROWS * NCHUNK];
__device__ float  g_tgt[4u * ROWS];
__device__ double g_rowlp[4u * ROWS];
__device__ double g_seq[8];

/* ---------------- helpers ---------------- */
__device__ __forceinline__ uint32_t smem_u32(const void* p) {
    uint32_t a;
    asm("{ .reg .u64 t; cvta.to.shared.u64 t, %1; cvt.u32.u64 %0, t; }" : "=r"(a) : "l"(p));
    return a;
}
__device__ __forceinline__ void cpa16(uint32_t dst, const void* src) {
    asm volatile("cp.async.cg.shared.global [%0], [%1], 16;" :: "r"(dst), "l"(src));
}
__device__ __forceinline__ void ldsm4(uint32_t& r0, uint32_t& r1, uint32_t& r2, uint32_t& r3,
                                      uint32_t a) {
    asm volatile("ldmatrix.sync.aligned.m8n8.x4.shared.b16 {%0,%1,%2,%3}, [%4];"
                 : "=r"(r0), "=r"(r1), "=r"(r2), "=r"(r3) : "r"(a));
}
__device__ __forceinline__ void mma16816(float* c, const uint32_t* a, const uint32_t* b) {
    asm volatile(
        "mma.sync.aligned.m16n8k16.row.col.f32.f16.f16.f32 "
        "{%0,%1,%2,%3}, {%4,%5,%6,%7}, {%8,%9}, {%0,%1,%2,%3};"
        : "+f"(c[0]), "+f"(c[1]), "+f"(c[2]), "+f"(c[3])
        : "r"(a[0]), "r"(a[1]), "r"(a[2]), "r"(a[3]), "r"(b[0]), "r"(b[1]));
}

/* ---------------- prep: fp32 -> fp16 (dest resolved IN DEVICE CODE) -------- */
__global__ void conv_f16(const float4* __restrict__ src, int which, size_t elem_off, int n4)
{
    int i = blockIdx.x * blockDim.x + threadIdx.x;
    if (i >= n4) return;
    float4 v = src[i];
    __half2 p0 = __floats2half2_rn(v.x, v.y);
    __half2 p1 = __floats2half2_rn(v.z, v.w);
    uint2 u;
    u.x = *reinterpret_cast<unsigned*>(&p0);
    u.y = *reinterpret_cast<unsigned*>(&p1);
    __half* dst = which ? g_Wf : g_Af;       /* device-side symbol resolution */
    reinterpret_cast<uint2*>(dst + elem_off)[i] = u;
}

/* ---------------- HMMA single-pass GEMM + exp-sum epilogue ---------------- */
/* stage: [A 16K][W 16K] = 32KB, 3 stages = 96KB per CTA, 2 CTAs/SM */
#define STG 32768u
__global__ void __launch_bounds__(256, 2) gemm_lse(const float* __restrict__ bp,
                                                   const float* __restrict__ br)
{
    extern __shared__ char sm[];
    const uint32_t sb = smem_u32(sm);
    const int tid  = threadIdx.x;
    const int wid  = tid >> 5, lane = tid & 31;
    const int wy   = wid >> 2;          /* 0..1 : m-offset wy*64 */
    const int wx   = wid & 3;           /* 0..3 : n-offset wx*32 */

    const int mt    = blockIdx.x;       /* m fastest -> W reuse in L2 */
    const int combo = mt >> 3;
    const int m0    = (mt & 7) * MT;
    const int n0    = blockIdx.y * NT;
    const float* bias = (combo < 2) ? bp : br;

    const size_t aoff = (size_t)(combo * ROWS + m0) * H_;
    const size_t boff = ((size_t)(combo >> 1) * V_ + n0) * H_;

    /* load tasks: each subtile 128 rows x 8 chunks(16B) = 1024 vec; 256 thr x 4 */
    uint32_t gOff[4], sOff[4];
#pragma unroll
    for (int i = 0; i < 4; ++i) {
        int t = tid + 256 * i;
        int r = t >> 3, c = t & 7;
        gOff[i] = (uint32_t)(r * H_ + c * 8);
        sOff[i] = (uint32_t)(r * 128 + ((c ^ (r & 7)) << 4));
    }

    auto load_chunk = [&](int c) {
        const uint32_t st = sb + (uint32_t)(c % 3) * STG;
        const uint32_t koff = (uint32_t)c * KCH;
#pragma unroll
        for (int i = 0; i < 4; ++i) {
            cpa16(st +         sOff[i], g_Af + aoff + gOff[i] + koff);
            cpa16(st + 16384 + sOff[i], g_Wf + boff + gOff[i] + koff);
        }
        asm volatile("cp.async.commit_group;");
    };

    float acc[4][4][4];
#pragma unroll
    for (int i = 0; i < 4; ++i)
#pragma unroll
        for (int j = 0; j < 4; ++j)
#pragma unroll
            for (int k = 0; k < 4; ++k) acc[i][j][k] = 0.f;

    load_chunk(0);
    load_chunk(1);

    for (int c = 0; c < KTILES; ++c) {
        if (c + 1 < KTILES) asm volatile("cp.async.wait_group 1;");
        else                asm volatile("cp.async.wait_group 0;");
        __syncthreads();                   /* data(c) visible; compute(c-1) done */
        if (c + 2 < KTILES) load_chunk(c + 2);

        const uint32_t st = sb + (uint32_t)(c % 3) * STG;
#pragma unroll
        for (int k16 = 0; k16 < 4; ++k16) {
            const int kc8 = k16 * 2 + (lane >> 4);
            uint32_t a[4][4];
#pragma unroll
            for (int mrep = 0; mrep < 4; ++mrep) {
                const int row = wy * 64 + mrep * 16 + (lane & 15);
                const uint32_t off = row * 128 + (((kc8 ^ (row & 7))) << 4);
                ldsm4(a[mrep][0], a[mrep][1], a[mrep][2], a[mrep][3], st + off);
            }
#pragma unroll
            for (int nh = 0; nh < 2; ++nh) {
                const int row = wx * 32 + nh * 16 + (lane & 15);
                const uint32_t off = row * 128 + (((kc8 ^ (row & 7))) << 4);
                uint32_t b[2][2];
                uint32_t r0, r1, r2, r3;
                ldsm4(r0, r1, r2, r3, st + 16384 + off);
                b[0][0] = r0; b[0][1] = r2;
                b[1][0] = r1; b[1][1] = r3;
#pragma unroll
                for (int mrep = 0; mrep < 4; ++mrep)
#pragma unroll
                    for (int nr = 0; nr < 2; ++nr)
                        mma16816(acc[mrep][nh * 2 + nr], a[mrep], b[nr]);
            }
        }
        /* no bottom sync: next-iter wait+sync protects stage reuse */
    }

    /* ---- epilogue: per-row sum of exp(logit + bias) ---- */
    const int g = lane >> 2, q = lane & 3;
    float b0[4], b1[4];
#pragma unroll
    for (int nrep = 0; nrep < 4; ++nrep) {
        const int col = n0 + wx * 32 + nrep * 8 + q * 2;
        b0[nrep] = __ldg(&bias[col]);
        b1[nrep] = __ldg(&bias[col + 1]);
    }

    float* redf = (float*)sm;   /* stage-0 A area is dead after the loop */
#pragma unroll
    for (int mrep = 0; mrep < 4; ++mrep) {
        float s0 = 0.f, s1 = 0.f;
#pragma unroll
        for (int nrep = 0; nrep < 4; ++nrep) {
            s0 += expf(acc[mrep][nrep][0] + b0[nrep]) + expf(acc[mrep][nrep][1] + b1[nrep]);
            s1 += expf(acc[mrep][nrep][2] + b0[nrep]) + expf(acc[mrep][nrep][3] + b1[nrep]);
        }
        s0 += __shfl_xor_sync(0xFFFFFFFF, s0, 1);
        s0 += __shfl_xor_sync(0xFFFFFFFF, s0, 2);
        s1 += __shfl_xor_sync(0xFFFFFFFF, s1, 1);
        s1 += __shfl_xor_sync(0xFFFFFFFF, s1, 2);
        if (q == 0) {
            redf[(wy * 64 + mrep * 16 + g)     * 4 + wx] = s0;
            redf[(wy * 64 + mrep * 16 + 8 + g) * 4 + wx] = s1;
        }
    }
    __syncthreads();
    if (tid < 128) {
        const float s = redf[tid * 4] + redf[tid * 4 + 1] + redf[tid * 4 + 2] + redf[tid * 4 + 3];
        g_partial[(size_t)(combo * ROWS + m0 + tid) * NCHUNK + blockIdx.y] = s;
    }
}

/* ---------------- exact fp32 target logits (one warp per row) ---------------- */
__global__ void tgt_logits(const float* __restrict__ xc,  const float* __restrict__ xr,
                           const float* __restrict__ rxc, const float* __restrict__ rxr,
                           const float* __restrict__ Wp,  const float* __restrict__ Wr,
                           const float* __restrict__ bp,  const float* __restrict__ br,
                           const int*   __restrict__ tc,  const int*   __restrict__ tr)
{
    const int gw = blockIdx.x * 8 + (threadIdx.x >> 5);   /* 0..4095 */
    const int lane = threadIdx.x & 31;
    const int combo = gw >> 10;
    const int row   = gw & 1023;
    const float* x = (combo == 0) ? xc : (combo == 1) ? xr : (combo == 2) ? rxc : rxr;
    const float* w = (combo < 2) ? Wp : Wr;
    const float* b = (combo < 2) ? bp : br;
    const int*  tg = (combo & 1) ? tr : tc;

    const int t = __ldg(&tg[row]);
    float s = 0.f;
    if (t >= 0) {
        const float* xp = x + (size_t)row * H_;
        const float* wp = w + (size_t)t * H_;
        for (int k = lane; k < H_; k += 32) s += xp[k] * wp[k];
#pragma unroll
        for (int off = 16; off > 0; off >>= 1)
            s += __shfl_xor_sync(0xFFFFFFFF, s, off);
        s += __ldg(&b[t]);
    }
    if (lane == 0) g_tgt[combo * ROWS + row] = (t >= 0) ? s : 0.f;
}

/* ---------------- stage A: per-row token logp (one warp per row) ----------- */
__global__ void row_logp(const int* __restrict__ tc, const int* __restrict__ tr)
{
    const int gr   = blockIdx.x * 8 + (threadIdx.x >> 5);   /* 0..4095 */
    const int lane = threadIdx.x & 31;
    const int combo = gr >> 10;
    const int row   = gr & 1023;
    const int* tgt  = (combo & 1) ? tr : tc;

    const float* p = &g_partial[(size_t)gr * NCHUNK];
    double sum = 0.0;
    for (int j = lane; j < NCHUNK; j += 32) sum += (double)p[j];
#pragma unroll
    for (int off = 16; off > 0; off >>= 1)
        sum += __shfl_xor_sync(0xFFFFFFFF, sum, off);
    if (lane == 0) {
        const int t = tgt[row];
        g_rowlp[gr] = (t >= 0) ? ((double)g_tgt[gr] - log(sum)) : 0.0;
    }
}

/* ---------------- stage B: per-(combo,batch) sequence sum ---------------- */
__global__ void seq_sum()
{
    const int cb = blockIdx.x;             /* combo*2 + b */
    __shared__ double sdata[256];
    const double* p = &g_rowlp[(cb >> 1) * ROWS + (cb & 1) * S_];
    double acc = p[threadIdx.x] + p[threadIdx.x + 256];
    sdata[threadIdx.x] = acc;
    __syncthreads();
    for (int off = 128; off > 0; off >>= 1) {
        if (threadIdx.x < off) sdata[threadIdx.x] += sdata[threadIdx.x + off];
        __syncthreads();
    }
    if (threadIdx.x == 0) g_seq[cb] = sdata[0];
}

/* ---------------- DPO scalars (double) ---------------- */
__device__ __forceinline__ double log_sigmoid_d(double z)
{
    return (z >= 0.0) ? -log1p(exp(-z)) : (z - log1p(exp(z)));
}

__global__ void finalize(float* __restrict__ out, int out_size)
{
    if (threadIdx.x != 0 || blockIdx.x != 0) return;
    double loss = 0.0, crs = 0.0, rrs = 0.0, margin = 0.0, accc = 0.0;
    for (int b = 0; b < B_; ++b) {
        const double cl  = g_seq[0 + b];
        const double rl  = g_seq[2 + b];
        const double rcl = g_seq[4 + b];
        const double rrl = g_seq[6 + b];
        const double cr = (double)BETA_ * (cl - rcl);
        const double rr = (double)BETA_ * (rl - rrl);
        const double z  = (double)BETA_ * ((cl - rl) - (rcl - rrl));
        loss   += -log_sigmoid_d(z);
        crs    += cr;
        rrs    += rr;
        margin += cr - rr;
        accc   += (cr > rr) ? 1.0 : 0.0;
    }
    const double invB = 1.0 / (double)B_;
    float vals[6] = {(float)(loss * invB), (float)(crs * invB), (float)(rrs * invB),
                     (float)(margin * invB), (float)(accc * invB), 0.f};
    for (int i = 0; i < out_size; ++i) out[i] = (i < 6) ? vals[i] : 0.f;
}

/* ---------------- launch ---------------- */
extern "C" void kernel_launch(void* const* d_in, const int* in_sizes, int n_in,
                              void* d_out, int out_size)
{
    const float* xc  = (const float*)d_in[0];
    const float* xr  = (const float*)d_in[1];
    const float* rxc = (const float*)d_in[2];
    const float* rxr = (const float*)d_in[3];
    const float* Wp  = (const float*)d_in[4];
    const float* bp  = (const float*)d_in[5];
    const float* Wr  = (const float*)d_in[6];
    const float* br  = (const float*)d_in[7];
    const int*   tc  = (const int*)d_in[8];
    const int*   tr  = (const int*)d_in[9];

    const int nA4 = ROWS * H_ / 4;                   /* 524288 */
    const int nW4 = (int)((size_t)V_ * H_ / 4);      /* 16384000 */
    conv_f16<<<(nA4 + 255) / 256, 256>>>((const float4*)xc,  0, 0 * (size_t)ROWS * H_, nA4);
    conv_f16<<<(nA4 + 255) / 256, 256>>>((const float4*)xr,  0, 1 * (size_t)ROWS * H_, nA4);
    conv_f16<<<(nA4 + 255) / 256, 256>>>((const float4*)rxc, 0, 2 * (size_t)ROWS * H_, nA4);
    conv_f16<<<(nA4 + 255) / 256, 256>>>((const float4*)rxr, 0, 3 * (size_t)ROWS * H_, nA4);
    conv_f16<<<(nW4 + 255) / 256, 256>>>((const float4*)Wp,  1, 0, nW4);
    conv_f16<<<(nW4 + 255) / 256, 256>>>((const float4*)Wr,  1, (size_t)V_ * H_, nW4);

    static const int SMEM_BYTES = 3 * 32768;         /* 98304 per CTA */
    cudaFuncSetAttribute(gemm_lse, cudaFuncAttributeMaxDynamicSharedMemorySize, SMEM_BYTES);
    dim3 gg(4 * ROWS / MT, V_ / NT);                 /* (32, 250) */
    gemm_lse<<<gg, 256, SMEM_BYTES>>>(bp, br);

    tgt_logits<<<512, 256>>>(xc, xr, rxc, rxr, Wp, Wr, bp, br, tc, tr);
    row_logp<<<512, 256>>>(tc, tr);
    seq_sum<<<8, 256>>>();
    finalize<<<1, 1>>>((float*)d_out, out_size);
}

// round 13
// speedup vs baseline: 13.3703x; 1.0312x over previous
#include <cuda_runtime.h>
#include <cuda_fp16.h>
#include <math.h>
#include <stdint.h>
#include <stddef.h>

#define B_    2
#define S_    512
#define H_    2048
#define V_    32000
#define BETA_ 0.1f

#define MT 128
#define NT 128
#define KCH 64                    /* K elems per stage chunk */
#define KTILES (H_/KCH)           /* 32 */
#define NCHUNK (V_/NT)            /* 250 */
#define ROWS  1024                /* B*S per combo */

/* ---------------- device scratch (static, allocation-free) ---------------- */
__device__ __align__(256) __half g_Af[4u * ROWS * H_];
__device__ __align__(256) __half g_Wf[2u * (size_t)V_ * H_];
__device__ float  g_partial[4u * ROWS * NCHUNK];
__device__ float  g_tgt[4u * ROWS];
__device__ double g_rowlp[4u * ROWS];
__device__ double g_seq[8];

/* ---------------- helpers ---------------- */
__device__ __forceinline__ uint32_t smem_u32(const void* p) {
    uint32_t a;
    asm("{ .reg .u64 t; cvta.to.shared.u64 t, %1; cvt.u32.u64 %0, t; }" : "=r"(a) : "l"(p));
    return a;
}
__device__ __forceinline__ void cpa16(uint32_t dst, const void* src) {
    asm volatile("cp.async.cg.shared.global [%0], [%1], 16;" :: "r"(dst), "l"(src));
}
__device__ __forceinline__ void ldsm4(uint32_t& r0, uint32_t& r1, uint32_t& r2, uint32_t& r3,
                                      uint32_t a) {
    asm volatile("ldmatrix.sync.aligned.m8n8.x4.shared.b16 {%0,%1,%2,%3}, [%4];"
                 : "=r"(r0), "=r"(r1), "=r"(r2), "=r"(r3) : "r"(a));
}
__device__ __forceinline__ void mma16816(float* c, const uint32_t* a, const uint32_t* b) {
    asm volatile(
        "mma.sync.aligned.m16n8k16.row.col.f32.f16.f16.f32 "
        "{%0,%1,%2,%3}, {%4,%5,%6,%7}, {%8,%9}, {%0,%1,%2,%3};"
        : "+f"(c[0]), "+f"(c[1]), "+f"(c[2]), "+f"(c[3])
        : "r"(a[0]), "r"(a[1]), "r"(a[2]), "r"(a[3]), "r"(b[0]), "r"(b[1]));
}

/* ---------------- prep: fp32 -> fp16 (dest resolved IN DEVICE CODE) -------- */
__global__ void conv_f16(const float4* __restrict__ src, int which, size_t elem_off, int n4)
{
    int i = blockIdx.x * blockDim.x + threadIdx.x;
    if (i >= n4) return;
    float4 v = src[i];
    __half2 p0 = __floats2half2_rn(v.x, v.y);
    __half2 p1 = __floats2half2_rn(v.z, v.w);
    uint2 u;
    u.x = *reinterpret_cast<unsigned*>(&p0);
    u.y = *reinterpret_cast<unsigned*>(&p1);
    __half* dst = which ? g_Wf : g_Af;       /* device-side symbol resolution */
    reinterpret_cast<uint2*>(dst + elem_off)[i] = u;
}

/* ---------------- HMMA single-pass GEMM + exp-sum epilogue ---------------- */
/* 128 threads (4 warps of 64x64). stage: [A 16K][W 16K] = 32KB, 3 stages = 96KB, 2 CTA/SM */
#define STG 32768u
__global__ void __launch_bounds__(128, 2) gemm_lse(const float* __restrict__ bp,
                                                   const float* __restrict__ br)
{
    extern __shared__ char sm[];
    const uint32_t sb = smem_u32(sm);
    const int tid  = threadIdx.x;
    const int wid  = tid >> 5, lane = tid & 31;
    const int wy   = wid >> 1;          /* 0..1 : m-offset wy*64 */
    const int wx   = wid & 1;           /* 0..1 : n-offset wx*64 */

    const int mt    = blockIdx.x;       /* m fastest -> W reuse in L2 */
    const int combo = mt >> 3;
    const int m0    = (mt & 7) * MT;
    const int n0    = blockIdx.y * NT;
    const float* bias = (combo < 2) ? bp : br;

    const size_t aoff = (size_t)(combo * ROWS + m0) * H_;
    const size_t boff = ((size_t)(combo >> 1) * V_ + n0) * H_;

    /* load tasks: each subtile 128 rows x 8 chunks(16B) = 1024 vec; 128 thr x 8 */
    uint32_t gOff[8], sOff[8];
#pragma unroll
    for (int i = 0; i < 8; ++i) {
        int t = tid + 128 * i;
        int r = t >> 3, c = t & 7;
        gOff[i] = (uint32_t)(r * H_ + c * 8);
        sOff[i] = (uint32_t)(r * 128 + ((c ^ (r & 7)) << 4));
    }

    auto load_chunk = [&](int c) {
        const uint32_t st = sb + (uint32_t)(c % 3) * STG;
        const uint32_t koff = (uint32_t)c * KCH;
#pragma unroll
        for (int i = 0; i < 8; ++i) {
            cpa16(st +         sOff[i], g_Af + aoff + gOff[i] + koff);
            cpa16(st + 16384 + sOff[i], g_Wf + boff + gOff[i] + koff);
        }
        asm volatile("cp.async.commit_group;");
    };

    float acc[4][8][4];
#pragma unroll
    for (int i = 0; i < 4; ++i)
#pragma unroll
        for (int j = 0; j < 8; ++j)
#pragma unroll
            for (int k = 0; k < 4; ++k) acc[i][j][k] = 0.f;

    load_chunk(0);
    load_chunk(1);

    for (int c = 0; c < KTILES; ++c) {
        if (c + 1 < KTILES) asm volatile("cp.async.wait_group 1;");
        else                asm volatile("cp.async.wait_group 0;");
        __syncthreads();                   /* data(c) visible; compute(c-1) done */
        if (c + 2 < KTILES) load_chunk(c + 2);

        const uint32_t st = sb + (uint32_t)(c % 3) * STG;
#pragma unroll
        for (int k16 = 0; k16 < 4; ++k16) {
            const int kc8 = k16 * 2 + (lane >> 4);
            uint32_t a[4][4];
#pragma unroll
            for (int mrep = 0; mrep < 4; ++mrep) {
                const int row = wy * 64 + mrep * 16 + (lane & 15);
                const uint32_t off = row * 128 + (((kc8 ^ (row & 7))) << 4);
                ldsm4(a[mrep][0], a[mrep][1], a[mrep][2], a[mrep][3], st + off);
            }
#pragma unroll
            for (int nh = 0; nh < 4; ++nh) {
                const int row = wx * 64 + nh * 16 + (lane & 15);
                const uint32_t off = row * 128 + (((kc8 ^ (row & 7))) << 4);
                uint32_t b[2][2];
                uint32_t r0, r1, r2, r3;
                ldsm4(r0, r1, r2, r3, st + 16384 + off);
                b[0][0] = r0; b[0][1] = r2;
                b[1][0] = r1; b[1][1] = r3;
#pragma unroll
                for (int mrep = 0; mrep < 4; ++mrep)
#pragma unroll
                    for (int nr = 0; nr < 2; ++nr)
                        mma16816(acc[mrep][nh * 2 + nr], a[mrep], b[nr]);
            }
        }
        /* no bottom sync: next-iter wait+sync protects stage reuse */
    }

    /* ---- epilogue: per-row sum of exp(logit + bias) ---- */
    const int g = lane >> 2, q = lane & 3;
    float b0[8], b1[8];
#pragma unroll
    for (int nrep = 0; nrep < 8; ++nrep) {
        const int col = n0 + wx * 64 + nrep * 8 + q * 2;
        b0[nrep] = __ldg(&bias[col]);
        b1[nrep] = __ldg(&bias[col + 1]);
    }

    float* redf = (float*)sm;   /* stage-0 A area is dead after the loop */
#pragma unroll
    for (int mrep = 0; mrep < 4; ++mrep) {
        float s0 = 0.f, s1 = 0.f;
#pragma unroll
        for (int nrep = 0; nrep < 8; ++nrep) {
            s0 += expf(acc[mrep][nrep][0] + b0[nrep]) + expf(acc[mrep][nrep][1] + b1[nrep]);
            s1 += expf(acc[mrep][nrep][2] + b0[nrep]) + expf(acc[mrep][nrep][3] + b1[nrep]);
        }
        s0 += __shfl_xor_sync(0xFFFFFFFF, s0, 1);
        s0 += __shfl_xor_sync(0xFFFFFFFF, s0, 2);
        s1 += __shfl_xor_sync(0xFFFFFFFF, s1, 1);
        s1 += __shfl_xor_sync(0xFFFFFFFF, s1, 2);
        if (q == 0) {
            redf[(wy * 64 + mrep * 16 + g)     * 2 + wx] = s0;
            redf[(wy * 64 + mrep * 16 + 8 + g) * 2 + wx] = s1;
        }
    }
    __syncthreads();
    /* 128 threads: one per row */
    {
        const float s = redf[tid * 2] + redf[tid * 2 + 1];
        g_partial[(size_t)(combo * ROWS + m0 + tid) * NCHUNK + blockIdx.y] = s;
    }
}

/* ---------------- exact fp32 target logits (one warp per row) ---------------- */
__global__ void tgt_logits(const float* __restrict__ xc,  const float* __restrict__ xr,
                           const float* __restrict__ rxc, const float* __restrict__ rxr,
                           const float* __restrict__ Wp,  const float* __restrict__ Wr,
                           const float* __restrict__ bp,  const float* __restrict__ br,
                           const int*   __restrict__ tc,  const int*   __restrict__ tr)
{
    const int gw = blockIdx.x * 8 + (threadIdx.x >> 5);   /* 0..4095 */
    const int lane = threadIdx.x & 31;
    const int combo = gw >> 10;
    const int row   = gw & 1023;
    const float* x = (combo == 0) ? xc : (combo == 1) ? xr : (combo == 2) ? rxc : rxr;
    const float* w = (combo < 2) ? Wp : Wr;
    const float* b = (combo < 2) ? bp : br;
    const int*  tg = (combo & 1) ? tr : tc;

    const int t = __ldg(&tg[row]);
    float s = 0.f;
    if (t >= 0) {
        const float* xp = x + (size_t)row * H_;
        const float* wp = w + (size_t)t * H_;
        for (int k = lane; k < H_; k += 32) s += xp[k] * wp[k];
#pragma unroll
        for (int off = 16; off > 0; off >>= 1)
            s += __shfl_xor_sync(0xFFFFFFFF, s, off);
        s += __ldg(&b[t]);
    }
    if (lane == 0) g_tgt[combo * ROWS + row] = (t >= 0) ? s : 0.f;
}

/* ---------------- stage A: per-row token logp (one warp per row) ----------- */
__global__ void row_logp(const int* __restrict__ tc, const int* __restrict__ tr)
{
    const int gr   = blockIdx.x * 8 + (threadIdx.x >> 5);   /* 0..4095 */
    const int lane = threadIdx.x & 31;
    const int combo = gr >> 10;
    const int row   = gr & 1023;
    const int* tgt  = (combo & 1) ? tr : tc;

    const float* p = &g_partial[(size_t)gr * NCHUNK];
    double sum = 0.0;
    for (int j = lane; j < NCHUNK; j += 32) sum += (double)p[j];
#pragma unroll
    for (int off = 16; off > 0; off >>= 1)
        sum += __shfl_xor_sync(0xFFFFFFFF, sum, off);
    if (lane == 0) {
        const int t = tgt[row];
        g_rowlp[gr] = (t >= 0) ? ((double)g_tgt[gr] - log(sum)) : 0.0;
    }
}

/* ---------------- stage B: per-(combo,batch) sequence sum ---------------- */
__global__ void seq_sum()
{
    const int cb = blockIdx.x;             /* combo*2 + b */
    __shared__ double sdata[256];
    const double* p = &g_rowlp[(cb >> 1) * ROWS + (cb & 1) * S_];
    double acc = p[threadIdx.x] + p[threadIdx.x + 256];
    sdata[threadIdx.x] = acc;
    __syncthreads();
    for (int off = 128; off > 0; off >>= 1) {
        if (threadIdx.x < off) sdata[threadIdx.x] += sdata[threadIdx.x + off];
        __syncthreads();
    }
    if (threadIdx.x == 0) g_seq[cb] = sdata[0];
}

/* ---------------- DPO scalars (double) ---------------- */
__device__ __forceinline__ double log_sigmoid_d(double z)
{
    return (z >= 0.0) ? -log1p(exp(-z)) : (z - log1p(exp(z)));
}

__global__ void finalize(float* __restrict__ out, int out_size)
{
    if (threadIdx.x != 0 || blockIdx.x != 0) return;
    double loss = 0.0, crs = 0.0, rrs = 0.0, margin = 0.0, accc = 0.0;
    for (int b = 0; b < B_; ++b) {
        const double cl  = g_seq[0 + b];
        const double rl  = g_seq[2 + b];
        const double rcl = g_seq[4 + b];
        const double rrl = g_seq[6 + b];
        const double cr = (double)BETA_ * (cl - rcl);
        const double rr = (double)BETA_ * (rl - rrl);
        const double z  = (double)BETA_ * ((cl - rl) - (rcl - rrl));
        loss   += -log_sigmoid_d(z);
        crs    += cr;
        rrs    += rr;
        margin += cr - rr;
        accc   += (cr > rr) ? 1.0 : 0.0;
    }
    const double invB = 1.0 / (double)B_;
    float vals[6] = {(float)(loss * invB), (float)(crs * invB), (float)(rrs * invB),
                     (float)(margin * invB), (float)(accc * invB), 0.f};
    for (int i = 0; i < out_size; ++i) out[i] = (i < 6) ? vals[i] : 0.f;
}

/* ---------------- launch ---------------- */
extern "C" void kernel_launch(void* const* d_in, const int* in_sizes, int n_in,
                              void* d_out, int out_size)
{
    const float* xc  = (const float*)d_in[0];
    const float* xr  = (const float*)d_in[1];
    const float* rxc = (const float*)d_in[2];
    const float* rxr = (const float*)d_in[3];
    const float* Wp  = (const float*)d_in[4];
    const float* bp  = (const float*)d_in[5];
    const float* Wr  = (const float*)d_in[6];
    const float* br  = (const float*)d_in[7];
    const int*   tc  = (const int*)d_in[8];
    const int*   tr  = (const int*)d_in[9];

    const int nA4 = ROWS * H_ / 4;                   /* 524288 */
    const int nW4 = (int)((size_t)V_ * H_ / 4);      /* 16384000 */
    conv_f16<<<(nA4 + 255) / 256, 256>>>((const float4*)xc,  0, 0 * (size_t)ROWS * H_, nA4);
    conv_f16<<<(nA4 + 255) / 256, 256>>>((const float4*)xr,  0, 1 * (size_t)ROWS * H_, nA4);
    conv_f16<<<(nA4 + 255) / 256, 256>>>((const float4*)rxc, 0, 2 * (size_t)ROWS * H_, nA4);
    conv_f16<<<(nA4 + 255) / 256, 256>>>((const float4*)rxr, 0, 3 * (size_t)ROWS * H_, nA4);
    conv_f16<<<(nW4 + 255) / 256, 256>>>((const float4*)Wp,  1, 0, nW4);
    conv_f16<<<(nW4 + 255) / 256, 256>>>((const float4*)Wr,  1, (size_t)V_ * H_, nW4);

    static const int SMEM_BYTES = 3 * 32768;         /* 98304 per CTA */
    cudaFuncSetAttribute(gemm_lse, cudaFuncAttributeMaxDynamicSharedMemorySize, SMEM_BYTES);
    dim3 gg(4 * ROWS / MT, V_ / NT);                 /* (32, 250) */
    gemm_lse<<<gg, 128, SMEM_BYTES>>>(bp, br);

    tgt_logits<<<512, 256>>>(xc, xr, rxc, rxr, Wp, Wr, bp, br, tc, tr);
    row_logp<<<512, 256>>>(tc, tr);
    seq_sum<<<8, 256>>>();
    finalize<<<1, 1>>>((float*)d_out, out_size);
}